// round 10
// baseline (speedup 1.0000x reference)
#include <cuda_runtime.h>
#include <math.h>

// ---------------------------------------------------------------------------
// MS-SSIM, 5 levels, 16x3x512x512 fp32 (48 planes). 3 launches:
//   ssim_level0 (fused full pool pyramid L1..L4), ssim_rest (levels 1..4),
//   final (parallel combine + re-zero of d_sums).
// Blur: 2 packed f32x2 streams (x,y) and (x^2+y^2, x*y).
// R10: 64-tall tiles (64x32 outputs). vblur = 8 warps x 8 rows (all threads
// active, 2.25x read amplification vs 3.5x). ~30% fewer LDS wavefronts per
// output on the binding L1 pipe. 66KB dynamic SMEM, 3 blocks/SM.
// ---------------------------------------------------------------------------

typedef unsigned long long u64;

__device__ __forceinline__ u64 pack2(float lo, float hi) {
    u64 r; asm("mov.b64 %0,{%1,%2};" : "=l"(r) : "f"(lo), "f"(hi)); return r;
}
__device__ __forceinline__ void unpack2(u64 v, float& lo, float& hi) {
    asm("mov.b64 {%0,%1},%2;" : "=f"(lo), "=f"(hi) : "l"(v));
}
__device__ __forceinline__ u64 fma2(u64 a, u64 b, u64 c) {
    u64 d; asm("fma.rn.f32x2 %0,%1,%2,%3;" : "=l"(d) : "l"(a), "l"(b), "l"(c)); return d;
}
__device__ __forceinline__ u64 mul2(u64 a, u64 b) {
    u64 d; asm("mul.rn.f32x2 %0,%1,%2;" : "=l"(d) : "l"(a), "l"(b)); return d;
}
__device__ __forceinline__ u64 add2(u64 a, u64 b) {
    u64 d; asm("add.rn.f32x2 %0,%1,%2;" : "=l"(d) : "l"(a), "l"(b)); return d;
}
__device__ __forceinline__ float sqrt_fast(float x) {
    float r; asm("sqrt.approx.f32 %0,%1;" : "=f"(r) : "f"(x)); return r;
}

#define TW 32
#define TH 64
#define EH 74          // TH + 10
#define EW 42
#define SIN_S 44       // u64 stride of input tile
#define SH_S  33       // stride of h-blurred maps

// dynamic SMEM layout (u64 units)
#define SIN_SZ (EH * SIN_S)            // 3256
#define SH_SZ  (EH * SH_S)             // 2442
#define SMEM_U64 (SIN_SZ + 2 * SH_SZ + 128 + 8)
#define SMEM_BYTES (SMEM_U64 * 8)      // 66208

// gaussian(sigma=1.5, 11 taps), normalized
#define G_0 0.00102838f
#define G_1 0.00759876f
#define G_2 0.03600088f
#define G_3 0.10936090f
#define G_4 0.21300530f
#define G_5 0.26601160f
#define GQ(t) G2c[(t) < 6 ? (t) : 10 - (t)]

// pooled pyramids (levels 1..4), 48 planes each
__device__ __align__(16) float d_Xp[4177920];
__device__ __align__(16) float d_Yp[4177920];
__device__ float d_sums[480];   // [level][img][2]  (zero-init; final re-zeros)

#define OFF1 0
#define OFF2 3145728
#define OFF3 3932160
#define OFF4 4128768

// core tile worker. POOL => level 0 (H=512, also emits L1..L4 pyramid).
template <bool POOL>
__device__ __forceinline__ void ssim_tile(
    const float* __restrict__ Xi, const float* __restrict__ Yi,
    int H, int level, int img, int bx, int by,
    float* __restrict__ Xp, float* __restrict__ Yp)
{
    extern __shared__ u64 dsm[];
    u64* sIN = dsm;                     // packed (x,y)
    u64* sMU = dsm + SIN_SZ;            // h-blurred (gx,gy)
    u64* sSP = dsm + SIN_SZ + SH_SZ;    // h-blurred (E[xx+yy], E[xy])
    u64* sL2 = dsm + SIN_SZ + 2 * SH_SZ;       // 16x8 L2 pool staging
    float* red = (float*)(sL2 + 128);   // [2][8]

    const int W = H;
    const int outH = H - 10;
    const int tx0 = bx * TW;
    const int ty0 = by * TH;
    const int tid = threadIdx.x;

    const u64 G2c[6] = {pack2(G_0,G_0), pack2(G_1,G_1), pack2(G_2,G_2),
                        pack2(G_3,G_3), pack2(G_4,G_4), pack2(G_5,G_5)};

    // ---- load extended tile, packed (x,y) -----------------------------------
    const bool interior = (tx0 + EW <= W) && (ty0 + EH <= H);
    if (interior) {
        // 74 rows x 21 col-pairs; float2 global loads
        for (int i = tid; i < EH * 21; i += 256) {
            int r = i / 21, c2 = i - r * 21;
            int c = c2 * 2;
            const float2 lx = *(const float2*)(Xi + (size_t)(ty0 + r) * W + tx0 + c);
            const float2 ly = *(const float2*)(Yi + (size_t)(ty0 + r) * W + tx0 + c);
            sIN[r * SIN_S + c]     = pack2(lx.x, ly.x);
            sIN[r * SIN_S + c + 1] = pack2(lx.y, ly.y);
        }
    } else {
        for (int i = tid; i < EH * EW; i += 256) {
            int r2 = i / EW, c2 = i - r2 * EW;
            int gr = ty0 + r2; if (gr > H - 1) gr = H - 1;
            int gc = tx0 + c2; if (gc > W - 1) gc = W - 1;
            sIN[r2 * SIN_S + c2] = pack2(Xi[(size_t)gr * W + gc], Yi[(size_t)gr * W + gc]);
        }
    }
    __syncthreads();

    // ---- fused pool pyramid (level 0 only): L1 (2/thread) + L2 --------------
    if (POOL) {
        const u64 QUARTER = pack2(0.25f, 0.25f);
        const int lane = tid & 31;
#pragma unroll
        for (int ii = 0; ii < 2; ii++) {
            int i = tid + ii * 256;             // 0..511
            int ph = i >> 4, pw = i & 15;       // ph 0..31, pw 0..15
            const u64* p0 = sIN + (ph * 2) * SIN_S + pw * 2;
            u64 v1 = mul2(add2(add2(p0[0], p0[1]), add2(p0[SIN_S], p0[SIN_S + 1])), QUARTER);
            {
                float a, b; unpack2(v1, a, b);
                size_t po = (size_t)img * 65536 + (size_t)(by * 32 + ph) * 256 + (bx * 16 + pw);
                (Xp + OFF1)[po] = a; (Yp + OFF1)[po] = b;
            }
            u64 s2 = add2(v1, __shfl_xor_sync(0xffffffffu, v1, 1));
            s2 = add2(s2, __shfl_xor_sync(0xffffffffu, s2, 16));
            if ((lane & 17) == 0) {
                u64 v2 = mul2(s2, QUARTER);
                int qh = i >> 5, qw = lane >> 1;   // qh 0..15, qw 0..7
                float a, b; unpack2(v2, a, b);
                size_t po = (size_t)img * 16384 + (size_t)(by * 16 + qh) * 128 + (bx * 8 + qw);
                (Xp + OFF2)[po] = a; (Yp + OFF2)[po] = b;
                sL2[qh * 8 + qw] = v2;
            }
        }
    }

    // ---- horizontal blur: 74 rows x 8 col-groups (4 outputs each) -----------
    {
        auto hblur = [&](int item) {
            int r = item >> 3, c4 = (item & 7) << 2;
            const u64* row = sIN + r * SIN_S + c4;
            u64 aMU[4] = {0,0,0,0}, aSP[4] = {0,0,0,0};
#pragma unroll
            for (int k = 0; k < 14; k++) {
                u64 v = row[k];
                float vx, vy; unpack2(v, vx, vy);
                u64 sp = pack2(fmaf(vx, vx, vy * vy), vx * vy);
#pragma unroll
                for (int q = 0; q < 4; q++) {
                    int t = k - q;
                    if (t >= 0 && t < 11) {
                        aMU[q] = fma2(v,  GQ(t), aMU[q]);
                        aSP[q] = fma2(sp, GQ(t), aSP[q]);
                    }
                }
            }
            int o = r * SH_S + c4;
#pragma unroll
            for (int q = 0; q < 4; q++) {
                sMU[o + q] = aMU[q];
                sSP[o + q] = aSP[q];
            }
        };
        hblur(tid);                                  // items 0..255
        hblur(tid + 256);                            // items 256..511
        if (tid < EH * 8 - 512) hblur(tid + 512);    // items 512..591
    }
    __syncthreads();

    // ---- pyramid tail: L3 (32 threads) + L4 (shuffles) ----------------------
    if (POOL && tid < 32) {
        const u64 QUARTER = pack2(0.25f, 0.25f);
        int rh = tid >> 2, rw = tid & 3;             // rh 0..7, rw 0..3
        const u64* q0 = sL2 + (rh * 2) * 8 + rw * 2;
        u64 v3 = mul2(add2(add2(q0[0], q0[1]), add2(q0[8], q0[9])), QUARTER);
        {
            float a, b; unpack2(v3, a, b);
            size_t po = (size_t)img * 4096 + (size_t)(by * 8 + rh) * 64 + (bx * 4 + rw);
            (Xp + OFF3)[po] = a; (Yp + OFF3)[po] = b;
        }
        u64 s4 = add2(v3, __shfl_xor_sync(0xffffffffu, v3, 1));
        s4 = add2(s4, __shfl_xor_sync(0xffffffffu, s4, 4));
        if ((tid & 5) == 0) {
            u64 v4 = mul2(s4, QUARTER);
            int sh = tid >> 3, sw = (tid >> 1) & 1;  // sh 0..3, sw 0..1
            float a, b; unpack2(v4, a, b);
            size_t po = (size_t)img * 1024 + (size_t)(by * 4 + sh) * 32 + (bx * 2 + sw);
            (Xp + OFF4)[po] = a; (Yp + OFF4)[po] = b;
        }
    }

    // ---- vertical blur: 8 warps x 8 rows (all 256 threads) + epilogue -------
    const float C1 = 1e-4f, C2 = 9e-4f;
    float d_acc = 0.f, cs_acc = 0.f;
    const int ty = tid >> 5, tx = tid & 31;
    const int rbase = ty * 8;
    {
        u64 aMU[8], aSP[8];
#pragma unroll
        for (int q = 0; q < 8; q++) { aMU[q] = 0; aSP[q] = 0; }
#pragma unroll
        for (int k = 0; k < 18; k++) {
            int row = (rbase + k) * SH_S + tx;
            u64 mu = sMU[row];
            u64 sp = sSP[row];
#pragma unroll
            for (int q = 0; q < 8; q++) {
                int t = k - q;
                if (t >= 0 && t < 11) {
                    aMU[q] = fma2(mu, GQ(t), aMU[q]);
                    aSP[q] = fma2(sp, GQ(t), aSP[q]);
                }
            }
        }
        const int ocol = tx0 + tx;
#pragma unroll
        for (int q = 0; q < 8; q++) {
            int orow = ty0 + rbase + q;
            if (orow < outH && ocol < outH) {
                float mu1, mu2, ess, exy;
                unpack2(aMU[q], mu1, mu2);
                unpack2(aSP[q], ess, exy);
                float mu1sq = mu1 * mu1, mu2sq = mu2 * mu2, mu12 = mu1 * mu2;
                float sig_sum = ess - mu1sq - mu2sq;
                float sig12 = exy - mu12;
                float S1 = __fdividef(2.f * mu12 + C1, mu1sq + mu2sq + C1);
                float S2 = __fdividef(2.f * sig12 + C2, sig_sum + C2);
                float S = fminf(S1 + S2, 2.0f);
                d_acc += sqrt_fast(2.0f - S);
                cs_acc += S2;
            }
        }
    }

    // ---- block reduce + atomic -----------------------------------------------
#pragma unroll
    for (int o = 16; o > 0; o >>= 1) {
        d_acc  += __shfl_down_sync(0xffffffffu, d_acc,  o);
        cs_acc += __shfl_down_sync(0xffffffffu, cs_acc, o);
    }
    if (tx == 0) { red[ty] = d_acc; red[8 + ty] = cs_acc; }
    __syncthreads();
    if (tid == 0) {
        float ds = 0.f, cs = 0.f;
#pragma unroll
        for (int j = 0; j < 8; j++) { ds += red[j]; cs += red[8 + j]; }
        atomicAdd(&d_sums[(level * 48 + img) * 2 + 0], ds);
        atomicAdd(&d_sums[(level * 48 + img) * 2 + 1], cs);
    }
}

__global__ void __launch_bounds__(256) ssim_level0_kernel(
    const float* __restrict__ X, const float* __restrict__ Y,
    float* __restrict__ Xp, float* __restrict__ Yp)
{
    const int img = blockIdx.z;
    const float* Xi = X + (size_t)img * 512 * 512;
    const float* Yi = Y + (size_t)img * 512 * 512;
    ssim_tile<true>(Xi, Yi, 512, 0, img, blockIdx.x, blockIdx.y, Xp, Yp);
}

// levels 1..4 in one grid of 2064 blocks
__global__ void __launch_bounds__(256) ssim_rest_kernel(
    const float* __restrict__ Xp, const float* __restrict__ Yp)
{
    int b = blockIdx.x;
    int level, H, ntx, nty, off, base;
    if (b < 1536)      { level = 1; H = 256; ntx = 8; nty = 4; off = OFF1; base = 0; }
    else if (b < 1920) { level = 2; H = 128; ntx = 4; nty = 2; off = OFF2; base = 1536; }
    else if (b < 2016) { level = 3; H = 64;  ntx = 2; nty = 1; off = OFF3; base = 1920; }
    else               { level = 4; H = 32;  ntx = 1; nty = 1; off = OFF4; base = 2016; }
    int rem = b - base;
    int tiles = ntx * nty;
    int img = rem / tiles;
    int t = rem - img * tiles;
    int by = t / ntx;
    int bx = t - by * ntx;
    const float* Xi = Xp + off + (size_t)img * H * H;
    const float* Yi = Yp + off + (size_t)img * H * H;
    ssim_tile<false>(Xi, Yi, H, level, img, bx, by, nullptr, nullptr);
}

__global__ void final_kernel(float* out, int out_size)
{
    __shared__ float part[2];
    const int i = threadIdx.x;       // 64 threads
    const float wts[5]  = {0.0448f, 0.2856f, 0.3001f, 0.2363f, 0.1333f};
    const float icnt[5] = {1.f/252004.f, 1.f/60516.f, 1.f/13924.f, 1.f/2916.f, 1.f/484.f};
    float v = 0.f;
    if (i < 48) {
        v = 1.f;
#pragma unroll
        for (int l = 0; l < 4; l++) {
            float csm = fmaxf(d_sums[(l * 48 + i) * 2 + 1] * icnt[l], 0.f);
            v *= __powf(csm, wts[l]);
        }
        float dm = fmaxf(d_sums[(4 * 48 + i) * 2 + 0] * icnt[4], 0.f);
        v *= __powf(dm, wts[4]);
    }
    float s = v;
#pragma unroll
    for (int o = 16; o > 0; o >>= 1) s += __shfl_down_sync(0xffffffffu, s, o);
    if ((i & 31) == 0) part[i >> 5] = s;
    __syncthreads();
    if (i == 0) {
        float r = (part[0] + part[1]) * (1.0f / 48.0f);
        for (int k = 0; k < out_size; k++) out[k] = r;
    }
    // restore invariant: d_sums zeroed for the next kernel_launch call
    __syncthreads();
    for (int j = i; j < 480; j += 64) d_sums[j] = 0.f;
}

extern "C" void kernel_launch(void* const* d_in, const int* in_sizes, int n_in,
                              void* d_out, int out_size)
{
    const float* X = (const float*)d_in[0];
    const float* Y = (const float*)d_in[1];
    float* out = (float*)d_out;

    float *Xp = nullptr, *Yp = nullptr;
    cudaGetSymbolAddress((void**)&Xp, d_Xp);
    cudaGetSymbolAddress((void**)&Yp, d_Yp);

    cudaFuncSetAttribute(ssim_level0_kernel,
                         cudaFuncAttributeMaxDynamicSharedMemorySize, SMEM_BYTES);
    cudaFuncSetAttribute(ssim_rest_kernel,
                         cudaFuncAttributeMaxDynamicSharedMemorySize, SMEM_BYTES);

    ssim_level0_kernel<<<dim3(16, 8, 48), 256, SMEM_BYTES>>>(X, Y, Xp, Yp);
    ssim_rest_kernel<<<2064, 256, SMEM_BYTES>>>(Xp, Yp);
    final_kernel<<<1, 64>>>(out, out_size);
}

// round 12
// speedup vs baseline: 1.2625x; 1.2625x over previous
#include <cuda_runtime.h>
#include <math.h>

// ---------------------------------------------------------------------------
// MS-SSIM, 5 levels, 16x3x512x512 fp32 (48 planes). 3 launches:
//   ssim_band0 : level 0 as 32-wide x 256-tall rolling bands (8 chunks of 32
//                rows, mod-42 row rings) + fused pool pyramid L1..L4.
//                Vertical halo loaded/h-blurred ONCE per band (-21% work).
//   ssim_rest  : levels 1..4 as independent tiles (champion structure).
//   final      : parallel weighted combine; re-zeros d_sums.
// Blur: 2 packed f32x2 streams (x,y) and (x^2+y^2, x*y), all fp32.
// ---------------------------------------------------------------------------

typedef unsigned long long u64;

__device__ __forceinline__ u64 pack2(float lo, float hi) {
    u64 r; asm("mov.b64 %0,{%1,%2};" : "=l"(r) : "f"(lo), "f"(hi)); return r;
}
__device__ __forceinline__ void unpack2(u64 v, float& lo, float& hi) {
    asm("mov.b64 {%0,%1},%2;" : "=f"(lo), "=f"(hi) : "l"(v));
}
__device__ __forceinline__ u64 fma2(u64 a, u64 b, u64 c) {
    u64 d; asm("fma.rn.f32x2 %0,%1,%2,%3;" : "=l"(d) : "l"(a), "l"(b), "l"(c)); return d;
}
__device__ __forceinline__ u64 mul2(u64 a, u64 b) {
    u64 d; asm("mul.rn.f32x2 %0,%1,%2;" : "=l"(d) : "l"(a), "l"(b)); return d;
}
__device__ __forceinline__ u64 add2(u64 a, u64 b) {
    u64 d; asm("add.rn.f32x2 %0,%1,%2;" : "=l"(d) : "l"(a), "l"(b)); return d;
}
__device__ __forceinline__ float sqrt_fast(float x) {
    float r; asm("sqrt.approx.f32 %0,%1;" : "=f"(r) : "f"(x)); return r;
}

#define TW 32
#define TH 32
#define EH 42
#define EW 42
#define SIN_S 44       // u64 stride of input tile/ring
#define SH_S  33       // stride of h-blurred maps

// gaussian(sigma=1.5, 11 taps), normalized
#define G_0 0.00102838f
#define G_1 0.00759876f
#define G_2 0.03600088f
#define G_3 0.10936090f
#define G_4 0.21300530f
#define G_5 0.26601160f

// pooled pyramids (levels 1..4), 48 planes each
__device__ __align__(16) float d_Xp[4177920];
__device__ __align__(16) float d_Yp[4177920];
__device__ float d_sums[480];   // [level][img][2]  (zero-init; final re-zeros)

#define OFF1 0
#define OFF2 3145728
#define OFF3 3932160
#define OFF4 4128768

#define C1V 1e-4f
#define C2V 9e-4f

// ===========================================================================
// Level 0: rolling band kernel. Grid (16, 2, 48). Band = cols bx*32..+31,
// rows byy*256..+255 processed as 8 chunks of 32 output rows.
// ===========================================================================
__global__ void __launch_bounds__(256) ssim_band0_kernel(
    const float* __restrict__ X, const float* __restrict__ Y,
    float* __restrict__ Xp, float* __restrict__ Yp)
{
    __shared__ u64 sIN[EH * SIN_S];   // ring: packed (x,y), slot = row mod 42
    __shared__ u64 sMU[EH * SH_S];    // ring: h-blurred (gx,gy)
    __shared__ u64 sSP[EH * SH_S];    // ring: h-blurred (E[xx+yy], E[xy])
    __shared__ u64 sL2[64];
    __shared__ float red[2][8];

    const int img = blockIdx.z;
    const int bx = blockIdx.x, byy = blockIdx.y;
    const int tx0 = bx * 32;
    const float* Xi = X + (size_t)img * 262144;
    const float* Yi = Y + (size_t)img * 262144;
    const int tid = threadIdx.x;
    const int ty = tid >> 5, tx = tid & 31;
    const bool colint = (tx0 + EW <= 512);

    const float gg[11] = {G_0,G_1,G_2,G_3,G_4,G_5,G_4,G_3,G_2,G_1,G_0};
    u64 G2r[11];
#pragma unroll
    for (int k = 0; k < 11; k++) G2r[k] = pack2(gg[k], gg[k]);

    float d_sum = 0.f, cs_sum = 0.f;
    int s0 = byy ? 4 : 0;                   // (byy*256) mod 42

    for (int c = 0; c < 8; c++) {
        const int oy = byy * 256 + c * 32;

        // ---- load new input rows into the ring -------------------------------
        {
            const int rstart = c ? (oy + 10) : oy;
            int sstart = c ? (s0 + 10) : s0; if (sstart >= 42) sstart -= 42;
            const int nrows = c ? 32 : 42;
            if (colint) {
                for (int i = tid; i < nrows * 21; i += 256) {
                    int r = i / 21, cc = (i - r * 21) * 2;
                    int gr = rstart + r; if (gr > 511) gr = 511;
                    int slot = sstart + r; if (slot >= 42) slot -= 42;
                    const float2 lx = *(const float2*)(Xi + (size_t)gr * 512 + tx0 + cc);
                    const float2 ly = *(const float2*)(Yi + (size_t)gr * 512 + tx0 + cc);
                    sIN[slot * SIN_S + cc]     = pack2(lx.x, ly.x);
                    sIN[slot * SIN_S + cc + 1] = pack2(lx.y, ly.y);
                }
            } else {
                for (int i = tid; i < nrows * EW; i += 256) {
                    int r = i / EW, cc = i - r * EW;
                    int gr = rstart + r; if (gr > 511) gr = 511;
                    int gc = tx0 + cc;   if (gc > 511) gc = 511;
                    int slot = sstart + r; if (slot >= 42) slot -= 42;
                    sIN[slot * SIN_S + cc] =
                        pack2(Xi[(size_t)gr * 512 + gc], Yi[(size_t)gr * 512 + gc]);
                }
            }
        }
        __syncthreads();

        // ---- fused pool pyramid: L1 + L2 for this chunk ----------------------
        {
            const u64 QUARTER = pack2(0.25f, 0.25f);
            const int lane = tid & 31;
            int ph = tid >> 4, pw = tid & 15;
            int sl = s0 + 2 * ph;  if (sl  >= 42) sl  -= 42;
            int sl2 = sl + 1;      if (sl2 >= 42) sl2 -= 42;
            const u64* p0 = sIN + sl  * SIN_S + pw * 2;
            const u64* p1 = sIN + sl2 * SIN_S + pw * 2;
            u64 v1 = mul2(add2(add2(p0[0], p0[1]), add2(p1[0], p1[1])), QUARTER);
            {
                float a, b; unpack2(v1, a, b);
                size_t po = (size_t)img * 65536
                          + (size_t)(byy * 128 + c * 16 + ph) * 256 + (bx * 16 + pw);
                (Xp + OFF1)[po] = a; (Yp + OFF1)[po] = b;
            }
            u64 s2v = add2(v1, __shfl_xor_sync(0xffffffffu, v1, 1));
            s2v = add2(s2v, __shfl_xor_sync(0xffffffffu, s2v, 16));
            if ((lane & 17) == 0) {
                u64 v2 = mul2(s2v, QUARTER);
                int qh = tid >> 5, qw = lane >> 1;
                float a, b; unpack2(v2, a, b);
                size_t po = (size_t)img * 16384
                          + (size_t)(byy * 64 + c * 8 + qh) * 128 + (bx * 8 + qw);
                (Xp + OFF2)[po] = a; (Yp + OFF2)[po] = b;
                sL2[qh * 8 + qw] = v2;
            }
        }

        // ---- hblur: only the NEW rows of this chunk --------------------------
        {
            const int start = c ? 10 : 0;
            auto hb = [&](int item) {
                int lr = item >> 3, c4 = (item & 7) << 2;
                int slot = s0 + start + lr; if (slot >= 42) slot -= 42;
                const u64* row = sIN + slot * SIN_S + c4;
                u64 aMU[4] = {0,0,0,0}, aSP[4] = {0,0,0,0};
#pragma unroll
                for (int k = 0; k < 14; k++) {
                    u64 v = row[k];
                    float vx, vy; unpack2(v, vx, vy);
                    u64 sp = pack2(fmaf(vx, vx, vy * vy), vx * vy);
#pragma unroll
                    for (int q = 0; q < 4; q++) {
                        int t = k - q;
                        if (t >= 0 && t < 11) {
                            aMU[q] = fma2(v,  G2r[t], aMU[q]);
                            aSP[q] = fma2(sp, G2r[t], aSP[q]);
                        }
                    }
                }
                int o = slot * SH_S + c4;
#pragma unroll
                for (int q = 0; q < 4; q++) {
                    sMU[o + q] = aMU[q];
                    sSP[o + q] = aSP[q];
                }
            };
            hb(tid);
            if (c == 0 && tid < 336 - 256) hb(tid + 256);
        }
        __syncthreads();

        // ---- pool tail: L3 + L4 for this chunk -------------------------------
        if (tid < 16) {
            const u64 QUARTER = pack2(0.25f, 0.25f);
            int rh = tid >> 2, rw = tid & 3;
            const u64* q0 = sL2 + (rh * 2) * 8 + rw * 2;
            u64 v3 = mul2(add2(add2(q0[0], q0[1]), add2(q0[8], q0[9])), QUARTER);
            {
                float a, b; unpack2(v3, a, b);
                size_t po = (size_t)img * 4096
                          + (size_t)(byy * 32 + c * 4 + rh) * 64 + (bx * 4 + rw);
                (Xp + OFF3)[po] = a; (Yp + OFF3)[po] = b;
            }
            u64 s4 = add2(v3, __shfl_xor_sync(0xffffu, v3, 1));
            s4 = add2(s4, __shfl_xor_sync(0xffffu, s4, 4));
            if ((tid & 5) == 0) {
                u64 v4 = mul2(s4, QUARTER);
                int sh = tid >> 3, sw = (tid >> 1) & 1;
                float a, b; unpack2(v4, a, b);
                size_t po = (size_t)img * 1024
                          + (size_t)(byy * 16 + c * 2 + sh) * 32 + (bx * 2 + sw);
                (Xp + OFF4)[po] = a; (Yp + OFF4)[po] = b;
            }
        }

        // ---- vblur (4 rows per thread) + epilogue ----------------------------
        {
            const int rbase = ty * 4;
            u64 aMU[4] = {0,0,0,0}, aSP[4] = {0,0,0,0};
            int slot = s0 + rbase; if (slot >= 42) slot -= 42;
#pragma unroll
            for (int k = 0; k < 14; k++) {
                u64 mu = sMU[slot * SH_S + tx];
                u64 sp = sSP[slot * SH_S + tx];
#pragma unroll
                for (int q = 0; q < 4; q++) {
                    int t = k - q;
                    if (t >= 0 && t < 11) {
                        aMU[q] = fma2(mu, G2r[t], aMU[q]);
                        aSP[q] = fma2(sp, G2r[t], aSP[q]);
                    }
                }
                slot++; if (slot == 42) slot = 0;
            }
            const int ocol = tx0 + tx;
#pragma unroll
            for (int q = 0; q < 4; q++) {
                int orow = oy + rbase + q;
                if (orow < 502 && ocol < 502) {
                    float mu1, mu2, ess, exy;
                    unpack2(aMU[q], mu1, mu2);
                    unpack2(aSP[q], ess, exy);
                    float mu1sq = mu1 * mu1, mu2sq = mu2 * mu2, mu12 = mu1 * mu2;
                    float sig_sum = ess - mu1sq - mu2sq;
                    float sig12 = exy - mu12;
                    float S1 = __fdividef(2.f * mu12 + C1V, mu1sq + mu2sq + C1V);
                    float S2 = __fdividef(2.f * sig12 + C2V, sig_sum + C2V);
                    float S = fminf(S1 + S2, 2.0f);
                    d_sum += sqrt_fast(2.0f - S);
                    cs_sum += S2;
                }
            }
        }

        s0 += 32; if (s0 >= 42) s0 -= 42;
        // No extra barrier needed: next load writes sIN (read only before the
        // post-load sync of this chunk); vblur touches only sMU/sSP, which the
        // next hblur overwrites only after the next post-load sync.
    }

    // ---- single block reduce + atomic (level 0) ------------------------------
#pragma unroll
    for (int o = 16; o > 0; o >>= 1) {
        d_sum  += __shfl_down_sync(0xffffffffu, d_sum,  o);
        cs_sum += __shfl_down_sync(0xffffffffu, cs_sum, o);
    }
    if (tx == 0) { red[0][ty] = d_sum; red[1][ty] = cs_sum; }
    __syncthreads();
    if (tid == 0) {
        float ds = 0.f, cs = 0.f;
#pragma unroll
        for (int j = 0; j < 8; j++) { ds += red[0][j]; cs += red[1][j]; }
        atomicAdd(&d_sums[img * 2 + 0], ds);
        atomicAdd(&d_sums[img * 2 + 1], cs);
    }
}

// ===========================================================================
// Levels 1..4: champion tile kernel, unchanged.
// ===========================================================================
__device__ __forceinline__ void ssim_tile_rest(
    const float* __restrict__ Xi, const float* __restrict__ Yi,
    int H, int level, int img, int bx, int by)
{
    __shared__ u64 sIN[EH * SIN_S];
    __shared__ u64 sMU[EH * SH_S];
    __shared__ u64 sSP[EH * SH_S];
    __shared__ float red[2][8];

    const int W = H;
    const int outH = H - 10;
    const int tx0 = bx * TW;
    const int ty0 = by * TH;
    const int tid = threadIdx.x;

    const float gg[11] = {G_0,G_1,G_2,G_3,G_4,G_5,G_4,G_3,G_2,G_1,G_0};
    u64 G2r[11];
#pragma unroll
    for (int k = 0; k < 11; k++) G2r[k] = pack2(gg[k], gg[k]);

    const bool interior = (tx0 + EW <= W) && (ty0 + EH <= H);
    {
        int r = tid / EW, c = tid - r * EW;
        if (interior) {
            const float* xp = Xi + (size_t)(ty0 + r) * W + (tx0 + c);
            const float* yp = Yi + (size_t)(ty0 + r) * W + (tx0 + c);
            int rr = r, cc = c;
#pragma unroll
            for (int it = 0; it < 7; it++) {
                if (it < 6 || tid < (EH * EW - 6 * 256)) {
                    sIN[rr * SIN_S + cc] = pack2(__ldg(xp), __ldg(yp));
                }
                cc += 4; rr += 6;
                xp += 6 * (size_t)W + 4; yp += 6 * (size_t)W + 4;
                if (cc >= EW) { cc -= EW; rr += 1; xp += W - EW; yp += W - EW; }
            }
        } else {
            for (int i = tid; i < EH * EW; i += 256) {
                int r2 = i / EW, c2 = i - r2 * EW;
                int gr = ty0 + r2; if (gr > H - 1) gr = H - 1;
                int gc = tx0 + c2; if (gc > W - 1) gc = W - 1;
                sIN[r2 * SIN_S + c2] = pack2(Xi[(size_t)gr * W + gc], Yi[(size_t)gr * W + gc]);
            }
        }
    }
    __syncthreads();

    {
        auto hblur = [&](int item) {
            int r = item >> 3, c4 = (item & 7) << 2;
            const u64* row = sIN + r * SIN_S + c4;
            u64 aMU[4] = {0,0,0,0}, aSP[4] = {0,0,0,0};
#pragma unroll
            for (int k = 0; k < 14; k++) {
                u64 v = row[k];
                float vx, vy; unpack2(v, vx, vy);
                u64 sp = pack2(fmaf(vx, vx, vy * vy), vx * vy);
#pragma unroll
                for (int q = 0; q < 4; q++) {
                    int t = k - q;
                    if (t >= 0 && t < 11) {
                        aMU[q] = fma2(v,  G2r[t], aMU[q]);
                        aSP[q] = fma2(sp, G2r[t], aSP[q]);
                    }
                }
            }
            int o = r * SH_S + c4;
#pragma unroll
            for (int q = 0; q < 4; q++) {
                sMU[o + q] = aMU[q];
                sSP[o + q] = aSP[q];
            }
        };
        hblur(tid);
        if (tid < EH * 8 - 256) hblur(tid + 256);
    }
    __syncthreads();

    float d_acc = 0.f, cs_acc = 0.f;
    const int ty = tid >> 5, tx = tid & 31;
    const int rbase = ty * 4;
    {
        u64 aMU[4] = {0,0,0,0}, aSP[4] = {0,0,0,0};
#pragma unroll
        for (int k = 0; k < 14; k++) {
            int row = (rbase + k) * SH_S + tx;
            u64 mu = sMU[row];
            u64 sp = sSP[row];
#pragma unroll
            for (int q = 0; q < 4; q++) {
                int t = k - q;
                if (t >= 0 && t < 11) {
                    aMU[q] = fma2(mu, G2r[t], aMU[q]);
                    aSP[q] = fma2(sp, G2r[t], aSP[q]);
                }
            }
        }
        const int ocol = tx0 + tx;
#pragma unroll
        for (int q = 0; q < 4; q++) {
            int orow = ty0 + rbase + q;
            if (orow < outH && ocol < outH) {
                float mu1, mu2, ess, exy;
                unpack2(aMU[q], mu1, mu2);
                unpack2(aSP[q], ess, exy);
                float mu1sq = mu1 * mu1, mu2sq = mu2 * mu2, mu12 = mu1 * mu2;
                float sig_sum = ess - mu1sq - mu2sq;
                float sig12 = exy - mu12;
                float S1 = __fdividef(2.f * mu12 + C1V, mu1sq + mu2sq + C1V);
                float S2 = __fdividef(2.f * sig12 + C2V, sig_sum + C2V);
                float S = fminf(S1 + S2, 2.0f);
                d_acc += sqrt_fast(2.0f - S);
                cs_acc += S2;
            }
        }
    }

#pragma unroll
    for (int o = 16; o > 0; o >>= 1) {
        d_acc  += __shfl_down_sync(0xffffffffu, d_acc,  o);
        cs_acc += __shfl_down_sync(0xffffffffu, cs_acc, o);
    }
    if (tx == 0) { red[0][ty] = d_acc; red[1][ty] = cs_acc; }
    __syncthreads();
    if (tid == 0) {
        float ds = 0.f, cs = 0.f;
#pragma unroll
        for (int j = 0; j < 8; j++) { ds += red[0][j]; cs += red[1][j]; }
        atomicAdd(&d_sums[(level * 48 + img) * 2 + 0], ds);
        atomicAdd(&d_sums[(level * 48 + img) * 2 + 1], cs);
    }
}

__global__ void __launch_bounds__(256) ssim_rest_kernel(
    const float* __restrict__ Xp, const float* __restrict__ Yp)
{
    int b = blockIdx.x;
    int level, H, nt, off, base;
    if (b < 3072)      { level = 1; H = 256; nt = 8; off = OFF1; base = 0; }
    else if (b < 3840) { level = 2; H = 128; nt = 4; off = OFF2; base = 3072; }
    else if (b < 4032) { level = 3; H = 64;  nt = 2; off = OFF3; base = 3840; }
    else               { level = 4; H = 32;  nt = 1; off = OFF4; base = 4032; }
    int rem = b - base;
    int tiles = nt * nt;
    int img = rem / tiles;
    int t = rem - img * tiles;
    int by = t / nt;
    int bx = t - by * nt;
    const float* Xi = Xp + off + (size_t)img * H * H;
    const float* Yi = Yp + off + (size_t)img * H * H;
    ssim_tile_rest(Xi, Yi, H, level, img, bx, by);
}

__global__ void final_kernel(float* out, int out_size)
{
    __shared__ float part[2];
    const int i = threadIdx.x;       // 64 threads
    const float wts[5]  = {0.0448f, 0.2856f, 0.3001f, 0.2363f, 0.1333f};
    const float icnt[5] = {1.f/252004.f, 1.f/60516.f, 1.f/13924.f, 1.f/2916.f, 1.f/484.f};
    float v = 0.f;
    if (i < 48) {
        v = 1.f;
#pragma unroll
        for (int l = 0; l < 4; l++) {
            float csm = fmaxf(d_sums[(l * 48 + i) * 2 + 1] * icnt[l], 0.f);
            v *= __powf(csm, wts[l]);
        }
        float dm = fmaxf(d_sums[(4 * 48 + i) * 2 + 0] * icnt[4], 0.f);
        v *= __powf(dm, wts[4]);
    }
    float s = v;
#pragma unroll
    for (int o = 16; o > 0; o >>= 1) s += __shfl_down_sync(0xffffffffu, s, o);
    if ((i & 31) == 0) part[i >> 5] = s;
    __syncthreads();
    if (i == 0) {
        float r = (part[0] + part[1]) * (1.0f / 48.0f);
        for (int k = 0; k < out_size; k++) out[k] = r;
    }
    // restore invariant: d_sums zeroed for the next kernel_launch call
    __syncthreads();
    for (int j = i; j < 480; j += 64) d_sums[j] = 0.f;
}

extern "C" void kernel_launch(void* const* d_in, const int* in_sizes, int n_in,
                              void* d_out, int out_size)
{
    const float* X = (const float*)d_in[0];
    const float* Y = (const float*)d_in[1];
    float* out = (float*)d_out;

    float *Xp = nullptr, *Yp = nullptr;
    cudaGetSymbolAddress((void**)&Xp, d_Xp);
    cudaGetSymbolAddress((void**)&Yp, d_Yp);

    ssim_band0_kernel<<<dim3(16, 2, 48), 256>>>(X, Y, Xp, Yp);
    ssim_rest_kernel<<<4080, 256>>>(Xp, Yp);
    final_kernel<<<1, 64>>>(out, out_size);
}